// round 1
// baseline (speedup 1.0000x reference)
#include <cuda_runtime.h>
#include <math.h>

#define NN 16384
#define DD 32
#define BM 128
#define BK 32
#define NC (NN / BK)
#define KCH 8

// 4 scratch matrices [NN x DD]: T1, T2, LP, HPc  (8 MB total)
__device__ float g_scr[4 * NN * DD];

#define PACKF2(d, f)   asm("mov.b64 %0, {%1, %1};" : "=l"(d) : "f"(f))
#define FMAF2(d, a, b) asm("fma.rn.f32x2 %0, %1, %2, %0;" : "+l"(d) : "l"(a), "l"(b))
#define UNPK(lo, hi, v) asm("mov.b64 {%0, %1}, %2;" : "=f"(lo), "=f"(hi) : "l"(v))

// One Chebyshev step fused with LP/HP accumulation.
// first=1:  acc = L@X ; Tout=acc ; LP = al0*X + al1*acc ; HP = ah0*X + ah1*acc
// first=0:  acc = L@Tin ; t = 2*acc - Tpv ; Tout=t ; LP += al1*t ; HP += ah1*t
__global__ __launch_bounds__(128, 1) void cheb_gemm(
    const float* __restrict__ Lg, const float* __restrict__ Tin,
    const float* __restrict__ Tpv, float* __restrict__ Tout,
    float* __restrict__ LP, float* __restrict__ HP,
    float al0, float al1, float ah0, float ah1, int first)
{
    // L tile row-major with odd pitch 33: conflict-free scalar LDS (rows lane+32i)
    // and conflict-free scalar STS from the transpose-free loader.
    __shared__ float Ls[2][BM][BK + 1];
    __shared__ float Xs[2][BK][DD];

    const int t    = threadIdx.x;
    const int lane = t & 31;
    const int w    = t >> 5;        // warp id = column group (8 cols per warp)
    const int row0 = blockIdx.x * BM;

    unsigned long long acc[4][4];   // 4 rows x 4 f32x2 pairs (8 cols)
#pragma unroll
    for (int i = 0; i < 4; i++)
#pragma unroll
        for (int q = 0; q < 4; q++) acc[i][q] = 0ull;

    float4 lreg[8], xreg[2];

    // prefetch chunk 0
#pragma unroll
    for (int j = 0; j < 8; j++) {
        int id = t + 128 * j;
        int r = id >> 3, k4 = id & 7;
        lreg[j] = *(const float4*)&Lg[(size_t)(row0 + r) * NN + 4 * k4];
    }
#pragma unroll
    for (int j = 0; j < 2; j++) {
        int id = t + 128 * j;
        int kx = id >> 3, c4 = id & 7;
        xreg[j] = *(const float4*)&Tin[kx * DD + 4 * c4];
    }

    int s = 0;
    for (int c = 0; c < NC; ++c) {
        // stage current chunk into smem
#pragma unroll
        for (int j = 0; j < 8; j++) {
            int id = t + 128 * j;
            int r = id >> 3, k4 = id & 7;
            Ls[s][r][4 * k4 + 0] = lreg[j].x;
            Ls[s][r][4 * k4 + 1] = lreg[j].y;
            Ls[s][r][4 * k4 + 2] = lreg[j].z;
            Ls[s][r][4 * k4 + 3] = lreg[j].w;
        }
#pragma unroll
        for (int j = 0; j < 2; j++) {
            int id = t + 128 * j;
            int kx = id >> 3, c4 = id & 7;
            *(float4*)&Xs[s][kx][4 * c4] = xreg[j];
        }
        __syncthreads();

        // prefetch next chunk into registers (latency overlapped with compute)
        if (c + 1 < NC) {
            const int kk = (c + 1) * BK;
#pragma unroll
            for (int j = 0; j < 8; j++) {
                int id = t + 128 * j;
                int r = id >> 3, k4 = id & 7;
                lreg[j] = *(const float4*)&Lg[(size_t)(row0 + r) * NN + kk + 4 * k4];
            }
#pragma unroll
            for (int j = 0; j < 2; j++) {
                int id = t + 128 * j;
                int kx = id >> 3, c4 = id & 7;
                xreg[j] = *(const float4*)&Tin[(kk + kx) * DD + 4 * c4];
            }
        }

        // compute: 32 k-steps, 16 FFMA2 each per thread
#pragma unroll
        for (int k = 0; k < BK; k++) {
            ulonglong2 xa = *(const ulonglong2*)&Xs[s][k][8 * w];
            ulonglong2 xb = *(const ulonglong2*)&Xs[s][k][8 * w + 4];
            float l0 = Ls[s][lane +  0][k];
            float l1 = Ls[s][lane + 32][k];
            float l2 = Ls[s][lane + 64][k];
            float l3 = Ls[s][lane + 96][k];
            unsigned long long p0, p1, p2, p3;
            PACKF2(p0, l0); PACKF2(p1, l1); PACKF2(p2, l2); PACKF2(p3, l3);
            FMAF2(acc[0][0], p0, xa.x); FMAF2(acc[0][1], p0, xa.y);
            FMAF2(acc[0][2], p0, xb.x); FMAF2(acc[0][3], p0, xb.y);
            FMAF2(acc[1][0], p1, xa.x); FMAF2(acc[1][1], p1, xa.y);
            FMAF2(acc[1][2], p1, xb.x); FMAF2(acc[1][3], p1, xb.y);
            FMAF2(acc[2][0], p2, xa.x); FMAF2(acc[2][1], p2, xa.y);
            FMAF2(acc[2][2], p2, xb.x); FMAF2(acc[2][3], p2, xb.y);
            FMAF2(acc[3][0], p3, xa.x); FMAF2(acc[3][1], p3, xa.y);
            FMAF2(acc[3][2], p3, xb.x); FMAF2(acc[3][3], p3, xb.y);
        }
        s ^= 1;
        __syncthreads();
    }

    // epilogue
    float res[4][8];
#pragma unroll
    for (int i = 0; i < 4; i++)
#pragma unroll
        for (int q = 0; q < 4; q++) UNPK(res[i][2 * q], res[i][2 * q + 1], acc[i][q]);

    const int cb = 8 * w;
#pragma unroll
    for (int i = 0; i < 4; i++) {
        size_t base = (size_t)(row0 + lane + 32 * i) * DD + cb;
        float4 o0 = make_float4(res[i][0], res[i][1], res[i][2], res[i][3]);
        float4 o1 = make_float4(res[i][4], res[i][5], res[i][6], res[i][7]);
        if (first) {
            float4 x0 = *(const float4*)&Tpv[base];
            float4 x1 = *(const float4*)&Tpv[base + 4];
            *(float4*)&Tout[base]     = o0;
            *(float4*)&Tout[base + 4] = o1;
            float4 v;
            v.x = al0 * x0.x + al1 * o0.x; v.y = al0 * x0.y + al1 * o0.y;
            v.z = al0 * x0.z + al1 * o0.z; v.w = al0 * x0.w + al1 * o0.w;
            *(float4*)&LP[base] = v;
            v.x = al0 * x1.x + al1 * o1.x; v.y = al0 * x1.y + al1 * o1.y;
            v.z = al0 * x1.z + al1 * o1.z; v.w = al0 * x1.w + al1 * o1.w;
            *(float4*)&LP[base + 4] = v;
            v.x = ah0 * x0.x + ah1 * o0.x; v.y = ah0 * x0.y + ah1 * o0.y;
            v.z = ah0 * x0.z + ah1 * o0.z; v.w = ah0 * x0.w + ah1 * o0.w;
            *(float4*)&HP[base] = v;
            v.x = ah0 * x1.x + ah1 * o1.x; v.y = ah0 * x1.y + ah1 * o1.y;
            v.z = ah0 * x1.z + ah1 * o1.z; v.w = ah0 * x1.w + ah1 * o1.w;
            *(float4*)&HP[base + 4] = v;
        } else {
            float4 p0 = *(const float4*)&Tpv[base];
            float4 p1 = *(const float4*)&Tpv[base + 4];
            float4 t0, t1;
            t0.x = 2.f * o0.x - p0.x; t0.y = 2.f * o0.y - p0.y;
            t0.z = 2.f * o0.z - p0.z; t0.w = 2.f * o0.w - p0.w;
            t1.x = 2.f * o1.x - p1.x; t1.y = 2.f * o1.y - p1.y;
            t1.z = 2.f * o1.z - p1.z; t1.w = 2.f * o1.w - p1.w;
            *(float4*)&Tout[base]     = t0;   // Tout may alias Tpv: same thread RMW, safe
            *(float4*)&Tout[base + 4] = t1;
            float4 v;
            v = *(const float4*)&LP[base];
            v.x += al1 * t0.x; v.y += al1 * t0.y; v.z += al1 * t0.z; v.w += al1 * t0.w;
            *(float4*)&LP[base] = v;
            v = *(const float4*)&LP[base + 4];
            v.x += al1 * t1.x; v.y += al1 * t1.y; v.z += al1 * t1.z; v.w += al1 * t1.w;
            *(float4*)&LP[base + 4] = v;
            v = *(const float4*)&HP[base];
            v.x += ah1 * t0.x; v.y += ah1 * t0.y; v.z += ah1 * t0.z; v.w += ah1 * t0.w;
            *(float4*)&HP[base] = v;
            v = *(const float4*)&HP[base + 4];
            v.x += ah1 * t1.x; v.y += ah1 * t1.y; v.z += ah1 * t1.z; v.w += ah1 * t1.w;
            *(float4*)&HP[base + 4] = v;
        }
    }
}

// HP = X - HPc ; H_lp = relu(LP@Wlp+blp) ; H_hp = relu(HP@Whp+bhp)
// Z = [H_lp, H_hp, X] @ Wf + bf
__global__ __launch_bounds__(256) void fuse_kernel(
    const float* __restrict__ LP, const float* __restrict__ HPc,
    const float* __restrict__ X,
    const float* __restrict__ Wlp, const float* __restrict__ blp,
    const float* __restrict__ Whp, const float* __restrict__ bhp,
    const float* __restrict__ Wf, const float* __restrict__ bf,
    float* __restrict__ Z)
{
    __shared__ float sWlp[DD * DD], sWhp[DD * DD], sWf[3 * DD * DD];
    __shared__ float sb[3][DD];
    __shared__ float sLP[8][DD], sHP[8][DD], sX[8][DD], sHl[8][DD], sHh[8][DD];

    const int j = threadIdx.x, rl = threadIdx.y;
    const int t = rl * DD + j;
    for (int i = t; i < DD * DD; i += 256) { sWlp[i] = Wlp[i]; sWhp[i] = Whp[i]; }
    for (int i = t; i < 3 * DD * DD; i += 256) sWf[i] = Wf[i];
    if (t < DD) { sb[0][t] = blp[t]; sb[1][t] = bhp[t]; sb[2][t] = bf[t]; }

    const int r = blockIdx.x * 8 + rl;
    float xv = X[r * DD + j];
    sX[rl][j]  = xv;
    sLP[rl][j] = LP[r * DD + j];
    sHP[rl][j] = xv - HPc[r * DD + j];
    __syncthreads();

    float a = sb[0][j], b = sb[1][j];
#pragma unroll
    for (int i = 0; i < DD; i++) {
        a = fmaf(sLP[rl][i], sWlp[i * DD + j], a);
        b = fmaf(sHP[rl][i], sWhp[i * DD + j], b);
    }
    sHl[rl][j] = fmaxf(a, 0.f);
    sHh[rl][j] = fmaxf(b, 0.f);
    __syncthreads();

    float z = sb[2][j];
#pragma unroll
    for (int i = 0; i < DD; i++) {
        z = fmaf(sHl[rl][i], sWf[i * DD + j], z);
        z = fmaf(sHh[rl][i], sWf[(DD + i) * DD + j], z);
        z = fmaf(sX[rl][i],  sWf[(2 * DD + i) * DD + j], z);
    }
    Z[r * DD + j] = z;
}

// a_k(tau) = (2 - d_k0) * (-1)^k * exp(-tau) * I_k(tau), same 40-term series as reference
static void cheb_coeffs_host(double tau, double* a)
{
    for (int k = 0; k <= KCH; k++) {
        double s = 0.0;
        for (int m = 0; m < 40; m++) {
            double num = pow(tau * 0.5, 2 * m + k);
            double fm = 1.0, fmk = 1.0;
            for (int i = 2; i <= m; i++)     fm  *= (double)i;
            for (int i = 2; i <= m + k; i++) fmk *= (double)i;
            s += num / (fm * fmk);
        }
        a[k] = (k ? 2.0 : 1.0) * ((k & 1) ? -1.0 : 1.0) * exp(-tau) * s;
    }
}

extern "C" void kernel_launch(void* const* d_in, const int* in_sizes, int n_in,
                              void* d_out, int out_size)
{
    const float* X   = (const float*)d_in[0];
    const float* Lg  = (const float*)d_in[1];
    const float* Wlp = (const float*)d_in[2];
    const float* blp = (const float*)d_in[3];
    const float* Whp = (const float*)d_in[4];
    const float* bhp = (const float*)d_in[5];
    const float* Wf  = (const float*)d_in[6];
    const float* bf  = (const float*)d_in[7];
    float* Z = (float*)d_out;

    void* sp = nullptr;
    cudaGetSymbolAddress(&sp, g_scr);
    float* T1  = (float*)sp;
    float* T2  = T1 + NN * DD;
    float* LPb = T2 + NN * DD;
    float* HPb = LPb + NN * DD;

    double al[KCH + 1], ah[KCH + 1];
    cheb_coeffs_host(0.5, al);
    cheb_coeffs_host(1.5, ah);

    // k=1: T1 = L@X ; LP/HP initialized with a0*X + a1*T1
    cheb_gemm<<<NN / BM, 128>>>(Lg, X, X, T1, LPb, HPb,
        (float)al[0], (float)al[1], (float)ah[0], (float)ah[1], 1);
    // k=2: T2 = 2*L@T1 - X
    cheb_gemm<<<NN / BM, 128>>>(Lg, T1, X, T2, LPb, HPb,
        0.f, (float)al[2], 0.f, (float)ah[2], 0);
    // k=3..8: in-place ping-pong (Tout overwrites Tprev)
    float* cur = T2;
    float* prev = T1;
    for (int k = 3; k <= KCH; k++) {
        cheb_gemm<<<NN / BM, 128>>>(Lg, cur, prev, prev, LPb, HPb,
            0.f, (float)al[k], 0.f, (float)ah[k], 0);
        float* tmp = cur; cur = prev; prev = tmp;
    }

    fuse_kernel<<<NN / 8, dim3(DD, 8)>>>(LPb, HPb, X, Wlp, blp, Whp, bhp, Wf, bf, Z);
}

// round 3
// speedup vs baseline: 1.7463x; 1.7463x over previous
#include <cuda_runtime.h>
#include <math.h>

#define NN 16384
#define DD 32
#define BM 64
#define BK 32
#define KSPLIT 4
#define KEXT (NN / KSPLIT)   // 4096
#define NCC (KEXT / BK)      // 128 chunks per CTA
#define LPITCH 36            // multiple of 4 (LDS.128-aligned), 36%32=4 -> bank rotation
#define KCH 8
#define ND (NN * DD)

// scratch: Part[4][NN][DD], T1, T2, LP, HPc  -> 8*ND floats = 16 MB
__device__ float g_scr[8 * ND];

#define PACKF2(d, f)    asm("mov.b64 %0, {%1, %1};" : "=l"(d) : "f"(f))
#define FMAF2(d, a, b)  asm("fma.rn.f32x2 %0, %1, %2, %0;" : "+l"(d) : "l"(a), "l"(b))
#define UNPK(lo, hi, v) asm("mov.b64 {%0, %1}, %2;" : "=f"(lo), "=f"(hi) : "l"(v))

// Partial GEMM: Part[ks][rows, cols] = L[rows, ks-kslice] @ Tin[ks-kslice, cols]
__global__ __launch_bounds__(128, 7) void cheb_part(
    const float* __restrict__ Lg, const float* __restrict__ Tin,
    float* __restrict__ Part)
{
    __shared__ float Ls[2][BM][LPITCH];
    __shared__ float Xs[2][BK][DD];

    const int t    = threadIdx.x;
    const int lane = t & 31;
    const int cg   = t >> 5;               // warp = column group (8 cols)
    const int row0 = blockIdx.x * BM;
    const int kb0  = blockIdx.y * KEXT;

    unsigned long long acc[2][4];          // 2 rows (lane, lane+32) x 8 cols
#pragma unroll
    for (int i = 0; i < 2; i++)
#pragma unroll
        for (int q = 0; q < 4; q++) acc[i][q] = 0ull;

    float4 lreg[4], xreg[2];

    // prefetch chunk 0
#pragma unroll
    for (int j = 0; j < 4; j++) {
        int id = t + 128 * j;              // 0..511 -> 64 rows x 8 float4
        int r = id >> 3, k4 = id & 7;
        lreg[j] = *(const float4*)&Lg[(size_t)(row0 + r) * NN + kb0 + 4 * k4];
    }
#pragma unroll
    for (int j = 0; j < 2; j++) {
        int id = t + 128 * j;              // 0..255 -> 32 k x 8 float4
        int kx = id >> 3, c4 = id & 7;
        xreg[j] = *(const float4*)&Tin[(size_t)(kb0 + kx) * DD + 4 * c4];
    }

    int s = 0;
    for (int c = 0; c < NCC; ++c) {
#pragma unroll
        for (int j = 0; j < 4; j++) {
            int id = t + 128 * j;
            int r = id >> 3, k4 = id & 7;
            *(float4*)&Ls[s][r][4 * k4] = lreg[j];
        }
#pragma unroll
        for (int j = 0; j < 2; j++) {
            int id = t + 128 * j;
            int kx = id >> 3, c4 = id & 7;
            *(float4*)&Xs[s][kx][4 * c4] = xreg[j];
        }
        __syncthreads();

        if (c + 1 < NCC) {
            const int kk = kb0 + (c + 1) * BK;
#pragma unroll
            for (int j = 0; j < 4; j++) {
                int id = t + 128 * j;
                int r = id >> 3, k4 = id & 7;
                lreg[j] = *(const float4*)&Lg[(size_t)(row0 + r) * NN + kk + 4 * k4];
            }
#pragma unroll
            for (int j = 0; j < 2; j++) {
                int id = t + 128 * j;
                int kx = id >> 3, c4 = id & 7;
                xreg[j] = *(const float4*)&Tin[(size_t)(kk + kx) * DD + 4 * c4];
            }
        }

        // 32 k-steps; L via one LDS.128 per row per 4 k
#pragma unroll
        for (int kg = 0; kg < BK / 4; kg++) {
            float4 la = *(const float4*)&Ls[s][lane][4 * kg];
            float4 lb = *(const float4*)&Ls[s][lane + 32][4 * kg];
            const float* lav = &la.x;
            const float* lbv = &lb.x;
#pragma unroll
            for (int j = 0; j < 4; j++) {
                int k = 4 * kg + j;
                ulonglong2 xa = *(const ulonglong2*)&Xs[s][k][8 * cg];
                ulonglong2 xb = *(const ulonglong2*)&Xs[s][k][8 * cg + 4];
                unsigned long long p0, p1;
                PACKF2(p0, lav[j]); PACKF2(p1, lbv[j]);
                FMAF2(acc[0][0], p0, xa.x); FMAF2(acc[0][1], p0, xa.y);
                FMAF2(acc[0][2], p0, xb.x); FMAF2(acc[0][3], p0, xb.y);
                FMAF2(acc[1][0], p1, xa.x); FMAF2(acc[1][1], p1, xa.y);
                FMAF2(acc[1][2], p1, xb.x); FMAF2(acc[1][3], p1, xb.y);
            }
        }
        s ^= 1;
        __syncthreads();
    }

    // write partials
    float res[2][8];
#pragma unroll
    for (int i = 0; i < 2; i++)
#pragma unroll
        for (int q = 0; q < 4; q++) UNPK(res[i][2 * q], res[i][2 * q + 1], acc[i][q]);

#pragma unroll
    for (int i = 0; i < 2; i++) {
        size_t base = ((size_t)blockIdx.y * NN + row0 + lane + 32 * i) * DD + 8 * cg;
        *(float4*)&Part[base]     = make_float4(res[i][0], res[i][1], res[i][2], res[i][3]);
        *(float4*)&Part[base + 4] = make_float4(res[i][4], res[i][5], res[i][6], res[i][7]);
    }
}

// Sum KSPLIT partials, apply Chebyshev recurrence + LP/HP accumulation.
// first=1: acc = L@X ; Tout = acc ; LP = al0*Tpv + al1*acc ; HP = ah0*Tpv + ah1*acc
// first=0: tc = 2*acc - Tpv ; Tout = tc ; LP += al1*tc ; HP += ah1*tc
__global__ __launch_bounds__(256) void cheb_reduce(
    const float* __restrict__ Part, const float* __restrict__ Tpv,
    float* __restrict__ Tout, float* __restrict__ LP, float* __restrict__ HP,
    float al0, float al1, float ah0, float ah1, int first)
{
    const size_t i = ((size_t)blockIdx.x * 256 + threadIdx.x) * 4;
    float4 a0 = *(const float4*)&Part[i];
    float4 a1 = *(const float4*)&Part[ND + i];
    float4 a2 = *(const float4*)&Part[2 * (size_t)ND + i];
    float4 a3 = *(const float4*)&Part[3 * (size_t)ND + i];
    float4 acc;
    acc.x = (a0.x + a1.x) + (a2.x + a3.x);
    acc.y = (a0.y + a1.y) + (a2.y + a3.y);
    acc.z = (a0.z + a1.z) + (a2.z + a3.z);
    acc.w = (a0.w + a1.w) + (a2.w + a3.w);

    float4 pv = *(const float4*)&Tpv[i];
    if (first) {
        *(float4*)&Tout[i] = acc;
        float4 v;
        v.x = al0 * pv.x + al1 * acc.x; v.y = al0 * pv.y + al1 * acc.y;
        v.z = al0 * pv.z + al1 * acc.z; v.w = al0 * pv.w + al1 * acc.w;
        *(float4*)&LP[i] = v;
        v.x = ah0 * pv.x + ah1 * acc.x; v.y = ah0 * pv.y + ah1 * acc.y;
        v.z = ah0 * pv.z + ah1 * acc.z; v.w = ah0 * pv.w + ah1 * acc.w;
        *(float4*)&HP[i] = v;
    } else {
        float4 tc;
        tc.x = 2.f * acc.x - pv.x; tc.y = 2.f * acc.y - pv.y;
        tc.z = 2.f * acc.z - pv.z; tc.w = 2.f * acc.w - pv.w;
        *(float4*)&Tout[i] = tc;           // may alias Tpv: same-thread RMW, safe
        float4 v = *(const float4*)&LP[i];
        v.x += al1 * tc.x; v.y += al1 * tc.y; v.z += al1 * tc.z; v.w += al1 * tc.w;
        *(float4*)&LP[i] = v;
        v = *(const float4*)&HP[i];
        v.x += ah1 * tc.x; v.y += ah1 * tc.y; v.z += ah1 * tc.z; v.w += ah1 * tc.w;
        *(float4*)&HP[i] = v;
    }
}

// HP = X - HPc ; H_lp = relu(LP@Wlp+blp) ; H_hp = relu(HP@Whp+bhp)
// Z = [H_lp, H_hp, X] @ Wf + bf
__global__ __launch_bounds__(256) void fuse_kernel(
    const float* __restrict__ LP, const float* __restrict__ HPc,
    const float* __restrict__ X,
    const float* __restrict__ Wlp, const float* __restrict__ blp,
    const float* __restrict__ Whp, const float* __restrict__ bhp,
    const float* __restrict__ Wf, const float* __restrict__ bf,
    float* __restrict__ Z)
{
    __shared__ float sWlp[DD * DD], sWhp[DD * DD], sWf[3 * DD * DD];
    __shared__ float sb[3][DD];
    __shared__ float sLP[8][DD], sHP[8][DD], sX[8][DD], sHl[8][DD], sHh[8][DD];

    const int j = threadIdx.x, rl = threadIdx.y;
    const int t = rl * DD + j;
    for (int i = t; i < DD * DD; i += 256) { sWlp[i] = Wlp[i]; sWhp[i] = Whp[i]; }
    for (int i = t; i < 3 * DD * DD; i += 256) sWf[i] = Wf[i];
    if (t < DD) { sb[0][t] = blp[t]; sb[1][t] = bhp[t]; sb[2][t] = bf[t]; }

    const int r = blockIdx.x * 8 + rl;
    float xv = X[r * DD + j];
    sX[rl][j]  = xv;
    sLP[rl][j] = LP[r * DD + j];
    sHP[rl][j] = xv - HPc[r * DD + j];
    __syncthreads();

    float a = sb[0][j], b = sb[1][j];
#pragma unroll
    for (int i = 0; i < DD; i++) {
        a = fmaf(sLP[rl][i], sWlp[i * DD + j], a);
        b = fmaf(sHP[rl][i], sWhp[i * DD + j], b);
    }
    sHl[rl][j] = fmaxf(a, 0.f);
    sHh[rl][j] = fmaxf(b, 0.f);
    __syncthreads();

    float z = sb[2][j];
#pragma unroll
    for (int i = 0; i < DD; i++) {
        z = fmaf(sHl[rl][i], sWf[i * DD + j], z);
        z = fmaf(sHh[rl][i], sWf[(DD + i) * DD + j], z);
        z = fmaf(sX[rl][i],  sWf[(2 * DD + i) * DD + j], z);
    }
    Z[r * DD + j] = z;
}

// a_k(tau) = (2 - d_k0) * (-1)^k * exp(-tau) * I_k(tau), 40-term series as reference
static void cheb_coeffs_host(double tau, double* a)
{
    for (int k = 0; k <= KCH; k++) {
        double s = 0.0;
        for (int m = 0; m < 40; m++) {
            double num = pow(tau * 0.5, 2 * m + k);
            double fm = 1.0, fmk = 1.0;
            for (int i = 2; i <= m; i++)     fm  *= (double)i;
            for (int i = 2; i <= m + k; i++) fmk *= (double)i;
            s += num / (fm * fmk);
        }
        a[k] = (k ? 2.0 : 1.0) * ((k & 1) ? -1.0 : 1.0) * exp(-tau) * s;
    }
}

extern "C" void kernel_launch(void* const* d_in, const int* in_sizes, int n_in,
                              void* d_out, int out_size)
{
    const float* X   = (const float*)d_in[0];
    const float* Lg  = (const float*)d_in[1];
    const float* Wlp = (const float*)d_in[2];
    const float* blp = (const float*)d_in[3];
    const float* Whp = (const float*)d_in[4];
    const float* bhp = (const float*)d_in[5];
    const float* Wf  = (const float*)d_in[6];
    const float* bf  = (const float*)d_in[7];
    float* Z = (float*)d_out;

    void* sp = nullptr;
    cudaGetSymbolAddress(&sp, g_scr);
    float* Part = (float*)sp;              // 4*ND
    float* T1   = Part + 4 * (size_t)ND;
    float* T2   = T1 + ND;
    float* LPb  = T2 + ND;
    float* HPb  = LPb + ND;

    double al[KCH + 1], ah[KCH + 1];
    cheb_coeffs_host(0.5, al);
    cheb_coeffs_host(1.5, ah);

    const dim3 gg(NN / BM, KSPLIT);

    // k=1: T1 = L@X ; LP/HP init
    cheb_part<<<gg, 128>>>(Lg, X, Part);
    cheb_reduce<<<ND / 1024, 256>>>(Part, X, T1, LPb, HPb,
        (float)al[0], (float)al[1], (float)ah[0], (float)ah[1], 1);
    // k=2: T2 = 2*L@T1 - X
    cheb_part<<<gg, 128>>>(Lg, T1, Part);
    cheb_reduce<<<ND / 1024, 256>>>(Part, X, T2, LPb, HPb,
        0.f, (float)al[2], 0.f, (float)ah[2], 0);
    // k=3..8: ping-pong, Tout overwrites Tprev
    float* cur = T2;
    float* prev = T1;
    for (int k = 3; k <= KCH; k++) {
        cheb_part<<<gg, 128>>>(Lg, cur, Part);
        cheb_reduce<<<ND / 1024, 256>>>(Part, prev, prev, LPb, HPb,
            0.f, (float)al[k], 0.f, (float)ah[k], 0);
        float* tmp = cur; cur = prev; prev = tmp;
    }

    fuse_kernel<<<NN / 8, dim3(DD, 8)>>>(LPb, HPb, X, Wlp, blp, Whp, bhp, Wf, bf, Z);
}